// round 14
// baseline (speedup 1.0000x reference)
#include <cuda_runtime.h>
#include <cuda_fp16.h>

#define E_DIM   1024
#define M_TOT   4096
#define SEQ     2048
#define NBATCH  32
#define HD      64

// scratch
__device__ __half g_xh[M_TOT * E_DIM];
__device__ __half g_Wh[3 * E_DIM * E_DIM];    // Wq | Wk | Wv stacked [3072,1024]
__device__ __half g_Kh[M_TOT * E_DIM];
__device__ __half g_Vh[M_TOT * E_DIM];
__device__ float  g_Tp[NBATCH * 8 * HD * HD]; // 8 partials of K^T V per n
__device__ int    g_cnt[NBATCH];              // T-partial producers (8 per n)
__device__ int    g_cnt_w[16];                // Wk/Wv block converters (32 per blk)
__device__ int    g_cnt_q[8];                 // Wq block converters (32 per blk)

__device__ __forceinline__ unsigned su32(const void* p) {
    return (unsigned)__cvta_generic_to_shared(p);
}
#define CPA16(d, s) \
    asm volatile("cp.async.cg.shared.global [%0],[%1],16;" :: "r"(d), "l"(s))
#define CP_COMMIT() asm volatile("cp.async.commit_group;")
#define CP_WAIT(n)  asm volatile("cp.async.wait_group %0;" :: "n"(n))

#define LDSM_X4(r0, r1, r2, r3, p) \
    asm volatile("ldmatrix.sync.aligned.m8n8.x4.shared.b16 {%0,%1,%2,%3},[%4];" \
                 : "=r"(r0), "=r"(r1), "=r"(r2), "=r"(r3) : "r"(p))
#define LDSM_X4T(r0, r1, r2, r3, p) \
    asm volatile("ldmatrix.sync.aligned.m8n8.x4.trans.shared.b16 {%0,%1,%2,%3},[%4];" \
                 : "=r"(r0), "=r"(r1), "=r"(r2), "=r"(r3) : "r"(p))

#define MMA16(c, a, b0_, b1_) \
    asm volatile("mma.sync.aligned.m16n8k16.row.col.f32.f16.f16.f32 " \
                 "{%0,%1,%2,%3},{%4,%5,%6,%7},{%8,%9},{%0,%1,%2,%3};" \
                 : "+f"((c)[0]), "+f"((c)[1]), "+f"((c)[2]), "+f"((c)[3]) \
                 : "r"((a)[0]), "r"((a)[1]), "r"((a)[2]), "r"((a)[3]), \
                   "r"(b0_), "r"(b1_))

// Convert one float4 of f32 to a packed uint2 of 4 halfs.
__device__ __forceinline__ uint2 f4_to_h4(float4 v) {
    __half2 h0 = __floats2half2_rn(v.x, v.y);
    __half2 h1 = __floats2half2_rn(v.z, v.w);
    uint2 u;
    u.x = *(unsigned*)&h0;
    u.y = *(unsigned*)&h1;
    return u;
}

// ---------------------------------------------------------------------------
// cvt_x: f32 -> f16 for x ONLY (W conversion is distributed into the proj
// kernels). 1024 blocks x 4 float4/thread, packed 8B stores. Resets counters.
// ---------------------------------------------------------------------------
__global__ void cvt_x_kernel(const float* __restrict__ x)
{
    if (blockIdx.x == 0) {
        int t = threadIdx.x;
        if (t < NBATCH)           g_cnt[t] = 0;
        else if (t < NBATCH + 16) g_cnt_w[t - NBATCH] = 0;
        else if (t < NBATCH + 24) g_cnt_q[t - NBATCH - 16] = 0;
    }
    const float4* X4 = (const float4*)x;
    uint2* D = (uint2*)g_xh;
    const int base = blockIdx.x * 1024;
#pragma unroll
    for (int j = 0; j < 4; j++) {
        int off = base + threadIdx.x + j * 256;
        D[off] = f4_to_h4(X4[off]);
    }
}

// ---------------------------------------------------------------------------
// proj_kv: C[4096,2048] = X @ [Wk;Wv]^T + bias  -> g_Kh / g_Vh (f16)
// grid (32, 16): blockIdx.x = m-block (0..31), blockIdx.y = n-tile (0..15)
// so the 32 CTAs sharing a W n-block have CONTIGUOUS bids (co-resident).
// Prologue: each CTA converts 4 rows of its W block (f32->f16), 32-arrival
// counter sync. Then 128x128 GEMM, BK=64, 3-stage cp.async.
// ---------------------------------------------------------------------------
#define PJ_LD   72
#define PJ_STG  ((128 + 128) * PJ_LD)
#define PJ_SMEM (3 * PJ_STG * (int)sizeof(__half))   // 110592 B

__global__ __launch_bounds__(256, 2) void proj_kv_kernel(
    const float* __restrict__ wk, const float* __restrict__ wv,
    const float* __restrict__ bk, const float* __restrict__ bv)
{
    extern __shared__ __half sh[];

    const int tid  = threadIdx.x, lane = tid & 31;
    const int warp = tid >> 5, warpM = warp >> 2, warpN = warp & 3;
    const int g = lane >> 2, tg = lane & 3;
    const int quad = lane >> 3, rr = lane & 7;
    const int m0 = blockIdx.x * 128;      // m-block (bid-fast)
    const int n0 = blockIdx.y * 128;      // 0..2047 over Wk|Wv
    const int which = n0 >> 10;           // 0 -> K, 1 -> V

    // ---- distributed W conversion: 4 rows per CTA ----
    {
        const float* Wsrc = which ? wv : wk;
        const int rl = (n0 & 1023) + blockIdx.x * 4;   // source row base
        const int rg = E_DIM + n0 + blockIdx.x * 4;    // g_Wh row base
        const float4* W4 = (const float4*)Wsrc;
        uint2* Wd = (uint2*)g_Wh;
#pragma unroll
        for (int r = 0; r < 4; r++)
            Wd[(size_t)(rg + r) * 256 + tid] = f4_to_h4(W4[(size_t)(rl + r) * 256 + tid]);
        __threadfence();
        __syncthreads();
        if (tid == 0) {
            atomicAdd(&g_cnt_w[blockIdx.y], 1);
            while (atomicAdd(&g_cnt_w[blockIdx.y], 0) < 32) { }
        }
        __syncthreads();
        __threadfence();
    }

    float acc[4][4][4];
#pragma unroll
    for (int i = 0; i < 4; i++)
#pragma unroll
        for (int j = 0; j < 4; j++)
#pragma unroll
            for (int f = 0; f < 4; f++) acc[i][j][f] = 0.f;

#define PJ_FILL(st, k0, WROW0)                                                \
    do {                                                                      \
        __half* Xs = sh + (st) * PJ_STG;                                      \
        __half* Ws = Xs + 128 * PJ_LD;                                        \
        _Pragma("unroll")                                                     \
        for (int t = 0; t < 4; t++) {                                         \
            int seg = tid + t * 256;                                          \
            int row = seg >> 3, c16 = seg & 7;                                \
            CPA16(su32(Xs + row * PJ_LD + c16 * 8),                           \
                  &g_xh[(size_t)(m0 + row) * E_DIM + (k0) + c16 * 8]);        \
        }                                                                     \
        _Pragma("unroll")                                                     \
        for (int t = 0; t < 4; t++) {                                         \
            int seg = tid + t * 256;                                          \
            int row = seg >> 3, c16 = seg & 7;                                \
            CPA16(su32(Ws + row * PJ_LD + c16 * 8),                           \
                  &g_Wh[(size_t)((WROW0) + row) * E_DIM + (k0) + c16 * 8]);   \
        }                                                                     \
        CP_COMMIT();                                                          \
    } while (0)

    PJ_FILL(0, 0,  E_DIM + n0);
    PJ_FILL(1, 64, E_DIM + n0);

    const int NKT = E_DIM / 64;
    for (int kt = 0; kt < NKT; kt++) {
        const int st = kt % 3;
        if (kt < NKT - 1) { CP_WAIT(1); } else { CP_WAIT(0); }
        __syncthreads();

        const __half* Xs = sh + st * PJ_STG;
        const __half* Ws = Xs + 128 * PJ_LD;

#pragma unroll
        for (int ks = 0; ks < 4; ks++) {
            const int kb = ks * 16;
            unsigned a[4][4];
#pragma unroll
            for (int i = 0; i < 4; i++) {
                int row = warpM * 64 + i * 16 + ((quad & 1) << 3) + rr;
                int col = kb + ((quad >> 1) << 3);
                LDSM_X4(a[i][0], a[i][1], a[i][2], a[i][3],
                        su32(Xs + row * PJ_LD + col));
            }
#pragma unroll
            for (int jj = 0; jj < 2; jj++) {
                int nrow = warpN * 32 + jj * 16 + ((quad >> 1) << 3) + rr;
                int col  = kb + ((quad & 1) << 3);
                unsigned b0, b1, b2, b3;
                LDSM_X4(b0, b1, b2, b3, su32(Ws + nrow * PJ_LD + col));
#pragma unroll
                for (int i = 0; i < 4; i++) {
                    MMA16(acc[i][2 * jj],     a[i], b0, b1);
                    MMA16(acc[i][2 * jj + 1], a[i], b2, b3);
                }
            }
        }

        if (kt + 2 < NKT) PJ_FILL((kt + 2) % 3, (kt + 2) * 64, E_DIM + n0);
    }

    const int nbase = n0 & 1023;
    const float* bias = which ? bv : bk;
    __half* C = which ? g_Vh : g_Kh;

#pragma unroll
    for (int j = 0; j < 4; j++) {
        int col = nbase + warpN * 32 + j * 8 + tg * 2;
        float b0 = bias[col], b1 = bias[col + 1];
#pragma unroll
        for (int i = 0; i < 4; i++) {
            int rbase = m0 + warpM * 64 + i * 16;
            *(__half2*)&C[(size_t)(rbase + g) * E_DIM + col] =
                __floats2half2_rn(acc[i][j][0] + b0, acc[i][j][1] + b1);
            *(__half2*)&C[(size_t)(rbase + g + 8) * E_DIM + col] =
                __floats2half2_rn(acc[i][j][2] + b0, acc[i][j][3] + b1);
        }
    }
}

// ---------------------------------------------------------------------------
// proj_q: fused producer/consumer. grid (32, 8): blockIdx.x = batch n,
// blockIdx.y = chunk/n-tile ch  (32 CTAs per ch block have contiguous bids;
// all 256 CTAs co-resident).
// Prologue: convert 4 Wq rows (hidden behind phase 0).
// Phase 0: partial T over s'-rows [ch*256,+256) of batch n; publish; count.
// Phase 1: (after Wq-convert sync) q tile = X @ Wq^T, 3-stage pipeline.
// Phase 2: spin cnt[n]==8; reduce partials *0.125 -> f16; out = q @ T.
// ---------------------------------------------------------------------------
#define QST_LD 136
#define KV_LD  72

__global__ __launch_bounds__(256, 2) void proj_q_kernel(
    const float* __restrict__ wq, const float* __restrict__ bq,
    float* __restrict__ out)
{
    extern __shared__ __half sh[];

    const int tid  = threadIdx.x, lane = tid & 31;
    const int warp = tid >> 5, warpM = warp >> 2, warpN = warp & 3;
    const int g = lane >> 2, tg = lane & 3;
    const int quad = lane >> 3, rr = lane & 7;
    const int n  = blockIdx.x;            // batch n AND m-tile (m0 = 128*n)
    const int ch = blockIdx.y;            // partial chunk AND n-tile (h0 = 2*ch)
    const int m0 = n * 128;
    const int n0 = ch * 128;
    const int h0 = n0 >> 6;

    // ---- distributed Wq conversion: 4 rows per CTA (latency hidden by ph0)
    {
        const int rl = n0 + n * 4;        // Wq row (source == g_Wh row)
        const float4* W4 = (const float4*)wq;
        uint2* Wd = (uint2*)g_Wh;
#pragma unroll
        for (int r = 0; r < 4; r++)
            Wd[(size_t)(rl + r) * 256 + tid] = f4_to_h4(W4[(size_t)(rl + r) * 256 + tid]);
        __threadfence();
        __syncthreads();
        if (tid == 0) atomicAdd(&g_cnt_q[ch], 1);
    }

    // ================= Phase 0: producer — partial T[n][ch] ================
    {
        const __half* Kg = g_Kh + (size_t)n * SEQ * HD + (size_t)ch * 256 * HD;
        const __half* Vg = g_Vh + (size_t)n * SEQ * HD + (size_t)ch * 256 * HD;
        __half* Ksb = sh;                          // [2][64*KV_LD]
        __half* Vsb = sh + 2 * 64 * KV_LD;         // [2][64*KV_LD]

        const int mh = (warp >> 2) * 32;
        const int nb = (warp & 3) * 16;

        float accT[2][2][4];
#pragma unroll
        for (int mt = 0; mt < 2; mt++)
#pragma unroll
            for (int jn = 0; jn < 2; jn++)
#pragma unroll
                for (int f = 0; f < 4; f++) accT[mt][jn][f] = 0.f;

#define KVP_ISSUE(buf, k0)                                                    \
        do {                                                                  \
            _Pragma("unroll")                                                 \
            for (int t = 0; t < 2; t++) {                                     \
                int seg = tid + t * 256;                                      \
                int row = seg >> 3, s8 = seg & 7;                             \
                CPA16(su32(Ksb + (buf) * 64 * KV_LD + row * KV_LD + s8 * 8),  \
                      &Kg[(size_t)((k0) + row) * HD + s8 * 8]);               \
                CPA16(su32(Vsb + (buf) * 64 * KV_LD + row * KV_LD + s8 * 8),  \
                      &Vg[(size_t)((k0) + row) * HD + s8 * 8]);               \
            }                                                                 \
            CP_COMMIT();                                                      \
        } while (0)

        KVP_ISSUE(0, 0);

        for (int c = 0; c < 4; c++) {
            int buf = c & 1;
            __syncthreads();
            if (c < 3) { KVP_ISSUE(buf ^ 1, (c + 1) * 64); CP_WAIT(1); }
            else       { CP_WAIT(0); }
            __syncthreads();

            const __half* Ksx = Ksb + buf * 64 * KV_LD;
            const __half* Vsx = Vsb + buf * 64 * KV_LD;
#pragma unroll
            for (int ks = 0; ks < 4; ks++) {
                const int sb = ks * 16;
                unsigned a[2][4];
#pragma unroll
                for (int mt = 0; mt < 2; mt++) {
                    int row = sb + ((quad >> 1) << 3) + rr;
                    int col = mh + mt * 16 + ((quad & 1) << 3);
                    LDSM_X4T(a[mt][0], a[mt][1], a[mt][2], a[mt][3],
                             su32(Ksx + row * KV_LD + col));
                }
                int vrow = sb + ((quad & 1) << 3) + rr;
                int vcol = nb + ((quad >> 1) << 3);
                unsigned v0, v1, v2, v3;
                LDSM_X4T(v0, v1, v2, v3, su32(Vsx + vrow * KV_LD + vcol));
#pragma unroll
                for (int mt = 0; mt < 2; mt++) {
                    MMA16(accT[mt][0], a[mt], v0, v1);
                    MMA16(accT[mt][1], a[mt], v2, v3);
                }
            }
        }

        float* Tp = g_Tp + ((size_t)(n * 8 + ch)) * HD * HD;
#pragma unroll
        for (int mt = 0; mt < 2; mt++) {
            int dk0 = mh + mt * 16;
#pragma unroll
            for (int jn = 0; jn < 2; jn++) {
                int dv = nb + jn * 8 + tg * 2;
                *(float2*)&Tp[(dk0 + g) * HD + dv] =
                    make_float2(accT[mt][jn][0], accT[mt][jn][1]);
                *(float2*)&Tp[(dk0 + g + 8) * HD + dv] =
                    make_float2(accT[mt][jn][2], accT[mt][jn][3]);
            }
        }
        __threadfence();
        __syncthreads();
        if (tid == 0) atomicAdd(&g_cnt[n], 1);
        __syncthreads();
    }

    // ---- Wq conversion sync (32 arrivals; latency hidden by phase 0) ----
    if (tid == 0) {
        while (atomicAdd(&g_cnt_q[ch], 0) < 32) { }
    }
    __syncthreads();
    __threadfence();

    // ================= Phase 1: q tile GEMM =================
    float acc[4][4][4];
#pragma unroll
    for (int i = 0; i < 4; i++)
#pragma unroll
        for (int j = 0; j < 4; j++)
#pragma unroll
            for (int f = 0; f < 4; f++) acc[i][j][f] = 0.f;

    PJ_FILL(0, 0,  n0);
    PJ_FILL(1, 64, n0);

    const int NKT = E_DIM / 64;
    for (int kt = 0; kt < NKT; kt++) {
        const int st = kt % 3;
        if (kt < NKT - 1) { CP_WAIT(1); } else { CP_WAIT(0); }
        __syncthreads();

        const __half* Xs = sh + st * PJ_STG;
        const __half* Ws = Xs + 128 * PJ_LD;

#pragma unroll
        for (int ks = 0; ks < 4; ks++) {
            const int kb = ks * 16;
            unsigned a[4][4];
#pragma unroll
            for (int i = 0; i < 4; i++) {
                int row = warpM * 64 + i * 16 + ((quad & 1) << 3) + rr;
                int col = kb + ((quad >> 1) << 3);
                LDSM_X4(a[i][0], a[i][1], a[i][2], a[i][3],
                        su32(Xs + row * PJ_LD + col));
            }
#pragma unroll
            for (int jj = 0; jj < 2; jj++) {
                int nrow = warpN * 32 + jj * 16 + ((quad >> 1) << 3) + rr;
                int col  = kb + ((quad & 1) << 3);
                unsigned b0, b1, b2, b3;
                LDSM_X4(b0, b1, b2, b3, su32(Ws + nrow * PJ_LD + col));
#pragma unroll
                for (int i = 0; i < 4; i++) {
                    MMA16(acc[i][2 * jj],     a[i], b0, b1);
                    MMA16(acc[i][2 * jj + 1], a[i], b2, b3);
                }
            }
        }

        if (kt + 2 < NKT) PJ_FILL((kt + 2) % 3, (kt + 2) * 64, n0);
    }

    // ================= Phase 2: consumer — fused epilogue =================
    __syncthreads();                       // stage buffers free
    __half* Qst = sh;                      // [128][QST_LD]
    __half* Tst = sh + 128 * QST_LD;       // [64][72]

    // stage q tile (+bq) to Qst first (overlaps any residual spin)
#pragma unroll
    for (int j = 0; j < 4; j++) {
        int col = warpN * 32 + j * 8 + tg * 2;          // 0..127 local
        float b0 = bq[n0 + col], b1 = bq[n0 + col + 1];
#pragma unroll
        for (int i = 0; i < 4; i++) {
            int rl = warpM * 64 + i * 16;
            *(__half2*)&Qst[(rl + g) * QST_LD + col] =
                __floats2half2_rn(acc[i][j][0] + b0, acc[i][j][1] + b1);
            *(__half2*)&Qst[(rl + g + 8) * QST_LD + col] =
                __floats2half2_rn(acc[i][j][2] + b0, acc[i][j][3] + b1);
        }
    }

    // spin until all 8 partials for this n are published
    if (tid == 0) {
        while (atomicAdd(&g_cnt[n], 0) < 8) { }
    }
    __syncthreads();
    __threadfence();

    // reduce 8 partials -> Tst (f16, x0.125)
    {
        const float4* P = (const float4*)(g_Tp + (size_t)n * 8 * HD * HD);
#pragma unroll
        for (int t = 0; t < 4; t++) {
            int slot = tid + t * 256;        // 0..1023 float4 slots
            float4 s0 = P[slot];
#pragma unroll
            for (int p = 1; p < 8; p++) {
                float4 q = P[p * 1024 + slot];
                s0.x += q.x; s0.y += q.y; s0.z += q.z; s0.w += q.w;
            }
            int row = slot >> 4, col = (slot & 15) * 4;
            *(__half2*)&Tst[row * 72 + col] =
                __floats2half2_rn(s0.x * 0.125f, s0.y * 0.125f);
            *(__half2*)&Tst[row * 72 + col + 2] =
                __floats2half2_rn(s0.z * 0.125f, s0.w * 0.125f);
        }
    }
    __syncthreads();

    // warp w: head hl = w>>2, rows mb = (w&3)*32 .. +32
    const int hl = warp >> 2;
    const int mb = (warp & 3) * 32;

    float accF[2][4][2][4];
#pragma unroll
    for (int i = 0; i < 2; i++)
#pragma unroll
        for (int jj = 0; jj < 4; jj++)
#pragma unroll
            for (int jn = 0; jn < 2; jn++)
#pragma unroll
                for (int f = 0; f < 4; f++) accF[i][jj][jn][f] = 0.f;

#pragma unroll
    for (int k = 0; k < 4; k++) {
        const int kb = k * 16;
        unsigned a[2][4];
#pragma unroll
        for (int i = 0; i < 2; i++) {
            int row = mb + i * 16 + ((quad & 1) << 3) + rr;
            int col = hl * 64 + kb + ((quad >> 1) << 3);
            LDSM_X4(a[i][0], a[i][1], a[i][2], a[i][3],
                    su32(Qst + row * QST_LD + col));
        }
#pragma unroll
        for (int jj = 0; jj < 4; jj++) {
            int trow = kb + ((quad & 1) << 3) + rr;
            int tcol = jj * 16 + ((quad >> 1) << 3);
            unsigned v0, v1, v2, v3;
            LDSM_X4T(v0, v1, v2, v3, su32(Tst + trow * 72 + tcol));
#pragma unroll
            for (int i = 0; i < 2; i++) {
                MMA16(accF[i][jj][0], a[i], v0, v1);
                MMA16(accF[i][jj][1], a[i], v2, v3);
            }
        }
    }

    // store: out[(16*(m0+mloc) + h0+hl)*64 + d]
#pragma unroll
    for (int i = 0; i < 2; i++) {
        int mA = m0 + mb + i * 16 + g;
        int mB = mA + 8;
        size_t RA = (size_t)(16 * mA + h0 + hl) * HD;
        size_t RB = (size_t)(16 * mB + h0 + hl) * HD;
#pragma unroll
        for (int jj = 0; jj < 4; jj++) {
#pragma unroll
            for (int jn = 0; jn < 2; jn++) {
                int d = jj * 16 + jn * 8 + tg * 2;
                *(float2*)&out[RA + d] =
                    make_float2(accF[i][jj][jn][0], accF[i][jj][jn][1]);
                *(float2*)&out[RB + d] =
                    make_float2(accF[i][jj][jn][2], accF[i][jj][jn][3]);
            }
        }
    }
}

// ---------------------------------------------------------------------------
extern "C" void kernel_launch(void* const* d_in, const int* in_sizes, int n_in,
                              void* d_out, int out_size)
{
    const float* x  = (const float*)d_in[0];
    const float* Wq = (const float*)d_in[1];
    const float* bq = (const float*)d_in[2];
    const float* Wk = (const float*)d_in[3];
    const float* bk = (const float*)d_in[4];
    const float* Wv = (const float*)d_in[5];
    const float* bv = (const float*)d_in[6];
    float* out = (float*)d_out;

    cudaFuncSetAttribute(proj_kv_kernel,
                         cudaFuncAttributeMaxDynamicSharedMemorySize, PJ_SMEM);
    cudaFuncSetAttribute(proj_q_kernel,
                         cudaFuncAttributeMaxDynamicSharedMemorySize, PJ_SMEM);

    cvt_x_kernel<<<1024, 256>>>(x);

    proj_kv_kernel<<<dim3(32, 16), 256, PJ_SMEM>>>(Wk, Wv, bk, bv);

    proj_q_kernel<<<dim3(32, 8), 256, PJ_SMEM>>>(Wq, bq, out);
}

// round 15
// speedup vs baseline: 1.0608x; 1.0608x over previous
#include <cuda_runtime.h>
#include <cuda_fp16.h>

#define E_DIM   1024
#define M_TOT   4096
#define SEQ     2048
#define NBATCH  32
#define HD      64

// scratch
__device__ __half g_xh[M_TOT * E_DIM];
__device__ __half g_Wh[3 * E_DIM * E_DIM];    // Wq | Wk | Wv stacked [3072,1024]
__device__ __half g_Kh[M_TOT * E_DIM];
__device__ __half g_Vh[M_TOT * E_DIM];
__device__ float  g_Tp[NBATCH * 8 * HD * HD]; // 8 partials of K^T V per n
__device__ int    g_cnt[NBATCH];              // T-partial producers (8 per n)

__device__ __forceinline__ unsigned su32(const void* p) {
    return (unsigned)__cvta_generic_to_shared(p);
}
#define CPA16(d, s) \
    asm volatile("cp.async.cg.shared.global [%0],[%1],16;" :: "r"(d), "l"(s))
#define CP_COMMIT() asm volatile("cp.async.commit_group;")
#define CP_WAIT(n)  asm volatile("cp.async.wait_group %0;" :: "n"(n))

#define LDSM_X4(r0, r1, r2, r3, p) \
    asm volatile("ldmatrix.sync.aligned.m8n8.x4.shared.b16 {%0,%1,%2,%3},[%4];" \
                 : "=r"(r0), "=r"(r1), "=r"(r2), "=r"(r3) : "r"(p))
#define LDSM_X4T(r0, r1, r2, r3, p) \
    asm volatile("ldmatrix.sync.aligned.m8n8.x4.trans.shared.b16 {%0,%1,%2,%3},[%4];" \
                 : "=r"(r0), "=r"(r1), "=r"(r2), "=r"(r3) : "r"(p))

#define MMA16(c, a, b0_, b1_) \
    asm volatile("mma.sync.aligned.m16n8k16.row.col.f32.f16.f16.f32 " \
                 "{%0,%1,%2,%3},{%4,%5,%6,%7},{%8,%9},{%0,%1,%2,%3};" \
                 : "+f"((c)[0]), "+f"((c)[1]), "+f"((c)[2]), "+f"((c)[3]) \
                 : "r"((a)[0]), "r"((a)[1]), "r"((a)[2]), "r"((a)[3]), \
                   "r"(b0_), "r"(b1_))

// Convert two float4 (8 f32) to one uint4 (8 packed halfs).
__device__ __forceinline__ uint4 f8_to_h8(float4 a, float4 b) {
    __half2 h0 = __floats2half2_rn(a.x, a.y);
    __half2 h1 = __floats2half2_rn(a.z, a.w);
    __half2 h2 = __floats2half2_rn(b.x, b.y);
    __half2 h3 = __floats2half2_rn(b.z, b.w);
    uint4 u;
    u.x = *(unsigned*)&h0; u.y = *(unsigned*)&h1;
    u.z = *(unsigned*)&h2; u.w = *(unsigned*)&h3;
    return u;
}
__device__ __forceinline__ uint2 f4_to_h4(float4 v) {
    __half2 h0 = __floats2half2_rn(v.x, v.y);
    __half2 h1 = __floats2half2_rn(v.z, v.w);
    uint2 u;
    u.x = *(unsigned*)&h0; u.y = *(unsigned*)&h1;
    return u;
}

// ---------------------------------------------------------------------------
// cvt: f32 -> f16 for x, Wk, Wv ONLY (Wq conversion folded into proj_kv).
// uint4 (16B) stores: each thread handles 2 uint4 slots (2x2 float4 loads).
// blocks [0,1024): x   [1024,1280): Wk   [1280,1536): Wv. Resets counters.
// ---------------------------------------------------------------------------
__global__ void cvt_kernel(const float* __restrict__ x,
                           const float* __restrict__ wk,
                           const float* __restrict__ wv)
{
    if (blockIdx.x == 0 && threadIdx.x < NBATCH) g_cnt[threadIdx.x] = 0;
    const int b = blockIdx.x;
    const float* s; __half* d; int base;   // base in uint4 slots (512/block)
    if (b < 1024)      { s = x;  d = g_xh;                     base = b * 512; }
    else if (b < 1280) { s = wk; d = g_Wh + E_DIM * E_DIM;     base = (b - 1024) * 512; }
    else               { s = wv; d = g_Wh + 2 * E_DIM * E_DIM; base = (b - 1280) * 512; }
    const float4* S4 = (const float4*)s;
    uint4* D = (uint4*)d;
#pragma unroll
    for (int t = 0; t < 2; t++) {
        int slot = base + threadIdx.x + t * 256;
        D[slot] = f8_to_h8(S4[2 * slot], S4[2 * slot + 1]);
    }
}

// ---------------------------------------------------------------------------
// proj_kv: C[4096,2048] = X @ [Wk;Wv]^T + bias  -> g_Kh / g_Vh (f16)
// CTA 128x128, BK=64, 3-stage cp.async, 8 warps (2x4). grid (16, 32).
// Prologue: each CTA converts 2 Wq rows (sync-free; proj_q launch boundary
// guarantees visibility).
// ---------------------------------------------------------------------------
#define PJ_LD   72
#define PJ_STG  ((128 + 128) * PJ_LD)
#define PJ_SMEM (3 * PJ_STG * (int)sizeof(__half))   // 110592 B

__global__ __launch_bounds__(256, 2) void proj_kv_kernel(
    const float* __restrict__ wq,
    const float* __restrict__ bk, const float* __restrict__ bv)
{
    extern __shared__ __half sh[];

    const int tid  = threadIdx.x, lane = tid & 31;
    const int warp = tid >> 5, warpM = warp >> 2, warpN = warp & 3;
    const int g = lane >> 2, tg = lane & 3;
    const int quad = lane >> 3, rr = lane & 7;
    const int m0 = blockIdx.y * 128;
    const int n0 = blockIdx.x * 128;      // 0..2047 over Wk|Wv

    // ---- sync-free distributed Wq conversion: 2 rows per CTA ----
    {
        const int cid = blockIdx.x + (blockIdx.y << 4);   // 0..511
        const float4* W4 = (const float4*)wq;
        uint2* Wd = (uint2*)g_Wh;
#pragma unroll
        for (int r = 0; r < 2; r++) {
            int row = cid * 2 + r;
            Wd[(size_t)row * 256 + tid] = f4_to_h4(W4[(size_t)row * 256 + tid]);
        }
    }

    float acc[4][4][4];
#pragma unroll
    for (int i = 0; i < 4; i++)
#pragma unroll
        for (int j = 0; j < 4; j++)
#pragma unroll
            for (int f = 0; f < 4; f++) acc[i][j][f] = 0.f;

#define PJ_FILL(st, k0, WROW0)                                                \
    do {                                                                      \
        __half* Xs = sh + (st) * PJ_STG;                                      \
        __half* Ws = Xs + 128 * PJ_LD;                                        \
        _Pragma("unroll")                                                     \
        for (int t = 0; t < 4; t++) {                                         \
            int seg = tid + t * 256;                                          \
            int row = seg >> 3, c16 = seg & 7;                                \
            CPA16(su32(Xs + row * PJ_LD + c16 * 8),                           \
                  &g_xh[(size_t)(m0 + row) * E_DIM + (k0) + c16 * 8]);        \
        }                                                                     \
        _Pragma("unroll")                                                     \
        for (int t = 0; t < 4; t++) {                                         \
            int seg = tid + t * 256;                                          \
            int row = seg >> 3, c16 = seg & 7;                                \
            CPA16(su32(Ws + row * PJ_LD + c16 * 8),                           \
                  &g_Wh[(size_t)((WROW0) + row) * E_DIM + (k0) + c16 * 8]);   \
        }                                                                     \
        CP_COMMIT();                                                          \
    } while (0)

    PJ_FILL(0, 0,  E_DIM + n0);
    PJ_FILL(1, 64, E_DIM + n0);

    const int NKT = E_DIM / 64;
    for (int kt = 0; kt < NKT; kt++) {
        const int st = kt % 3;
        if (kt < NKT - 1) { CP_WAIT(1); } else { CP_WAIT(0); }
        __syncthreads();

        const __half* Xs = sh + st * PJ_STG;
        const __half* Ws = Xs + 128 * PJ_LD;

#pragma unroll
        for (int ks = 0; ks < 4; ks++) {
            const int kb = ks * 16;
            unsigned a[4][4];
#pragma unroll
            for (int i = 0; i < 4; i++) {
                int row = warpM * 64 + i * 16 + ((quad & 1) << 3) + rr;
                int col = kb + ((quad >> 1) << 3);
                LDSM_X4(a[i][0], a[i][1], a[i][2], a[i][3],
                        su32(Xs + row * PJ_LD + col));
            }
#pragma unroll
            for (int jj = 0; jj < 2; jj++) {
                int nrow = warpN * 32 + jj * 16 + ((quad >> 1) << 3) + rr;
                int col  = kb + ((quad & 1) << 3);
                unsigned b0, b1, b2, b3;
                LDSM_X4(b0, b1, b2, b3, su32(Ws + nrow * PJ_LD + col));
#pragma unroll
                for (int i = 0; i < 4; i++) {
                    MMA16(acc[i][2 * jj],     a[i], b0, b1);
                    MMA16(acc[i][2 * jj + 1], a[i], b2, b3);
                }
            }
        }

        if (kt + 2 < NKT) PJ_FILL((kt + 2) % 3, (kt + 2) * 64, E_DIM + n0);
    }

    const int which = n0 >> 10;           // 0 -> K, 1 -> V
    const int nbase = n0 & 1023;
    const float* bias = which ? bv : bk;
    __half* C = which ? g_Vh : g_Kh;

#pragma unroll
    for (int j = 0; j < 4; j++) {
        int col = nbase + warpN * 32 + j * 8 + tg * 2;
        float b0 = bias[col], b1 = bias[col + 1];
#pragma unroll
        for (int i = 0; i < 4; i++) {
            int rbase = m0 + warpM * 64 + i * 16;
            *(__half2*)&C[(size_t)(rbase + g) * E_DIM + col] =
                __floats2half2_rn(acc[i][j][0] + b0, acc[i][j][1] + b1);
            *(__half2*)&C[(size_t)(rbase + g + 8) * E_DIM + col] =
                __floats2half2_rn(acc[i][j][2] + b0, acc[i][j][3] + b1);
        }
    }
}

// ---------------------------------------------------------------------------
// proj_q: fused producer/consumer kernel. grid (8, 32), all 256 CTAs
// co-resident (occ=2 by launch_bounds + smem).
// Phase 0 (producer): partial T over s'-rows [ch*256,+256) of batch n;
//                     store f32 partial; fence; count++.
// Phase 1: q tile = X @ Wq^T (128x128 = 2 heads), 3-stage pipeline.
// Phase 2 (consumer): spin cnt[n]==8; reduce 8 partials *0.125 -> f16 smem;
//                     out rows R=16m+h: out[R] = q64(m,h) @ T[n].
// ---------------------------------------------------------------------------
#define QST_LD 136
#define KV_LD  72

__global__ __launch_bounds__(256, 2) void proj_q_kernel(
    const float* __restrict__ bq, float* __restrict__ out)
{
    extern __shared__ __half sh[];

    const int tid  = threadIdx.x, lane = tid & 31;
    const int warp = tid >> 5, warpM = warp >> 2, warpN = warp & 3;
    const int g = lane >> 2, tg = lane & 3;
    const int quad = lane >> 3, rr = lane & 7;
    const int ch = blockIdx.x;            // partial chunk AND n-tile (h0 = 2*ch)
    const int n  = blockIdx.y;            // batch n AND m-tile (m0 = 128*n)
    const int m0 = n * 128;
    const int n0 = ch * 128;
    const int h0 = n0 >> 6;

    // ================= Phase 0: producer — partial T[n][ch] ================
    {
        const __half* Kg = g_Kh + (size_t)n * SEQ * HD + (size_t)ch * 256 * HD;
        const __half* Vg = g_Vh + (size_t)n * SEQ * HD + (size_t)ch * 256 * HD;
        __half* Ksb = sh;                          // [2][64*KV_LD]
        __half* Vsb = sh + 2 * 64 * KV_LD;         // [2][64*KV_LD]

        const int mh = (warp >> 2) * 32;
        const int nb = (warp & 3) * 16;

        float accT[2][2][4];
#pragma unroll
        for (int mt = 0; mt < 2; mt++)
#pragma unroll
            for (int jn = 0; jn < 2; jn++)
#pragma unroll
                for (int f = 0; f < 4; f++) accT[mt][jn][f] = 0.f;

#define KVP_ISSUE(buf, k0)                                                    \
        do {                                                                  \
            _Pragma("unroll")                                                 \
            for (int t = 0; t < 2; t++) {                                     \
                int seg = tid + t * 256;                                      \
                int row = seg >> 3, s8 = seg & 7;                             \
                CPA16(su32(Ksb + (buf) * 64 * KV_LD + row * KV_LD + s8 * 8),  \
                      &Kg[(size_t)((k0) + row) * HD + s8 * 8]);               \
                CPA16(su32(Vsb + (buf) * 64 * KV_LD + row * KV_LD + s8 * 8),  \
                      &Vg[(size_t)((k0) + row) * HD + s8 * 8]);               \
            }                                                                 \
            CP_COMMIT();                                                      \
        } while (0)

        KVP_ISSUE(0, 0);

        for (int c = 0; c < 4; c++) {
            int buf = c & 1;
            __syncthreads();
            if (c < 3) { KVP_ISSUE(buf ^ 1, (c + 1) * 64); CP_WAIT(1); }
            else       { CP_WAIT(0); }
            __syncthreads();

            const __half* Ksx = Ksb + buf * 64 * KV_LD;
            const __half* Vsx = Vsb + buf * 64 * KV_LD;
#pragma unroll
            for (int ks = 0; ks < 4; ks++) {
                const int sb = ks * 16;
                unsigned a[2][4];
#pragma unroll
                for (int mt = 0; mt < 2; mt++) {
                    int row = sb + ((quad >> 1) << 3) + rr;
                    int col = mh + mt * 16 + ((quad & 1) << 3);
                    LDSM_X4T(a[mt][0], a[mt][1], a[mt][2], a[mt][3],
                             su32(Ksx + row * KV_LD + col));
                }
                int vrow = sb + ((quad & 1) << 3) + rr;
                int vcol = nb + ((quad >> 1) << 3);
                unsigned v0, v1, v2, v3;
                LDSM_X4T(v0, v1, v2, v3, su32(Vsx + vrow * KV_LD + vcol));
#pragma unroll
                for (int mt = 0; mt < 2; mt++) {
                    MMA16(accT[mt][0], a[mt], v0, v1);
                    MMA16(accT[mt][1], a[mt], v2, v3);
                }
            }
        }

        float* Tp = g_Tp + ((size_t)(n * 8 + ch)) * HD * HD;
#pragma unroll
        for (int mt = 0; mt < 2; mt++) {
            int dk0 = mh + mt * 16;
#pragma unroll
            for (int jn = 0; jn < 2; jn++) {
                int dv = nb + jn * 8 + tg * 2;
                *(float2*)&Tp[(dk0 + g) * HD + dv] =
                    make_float2(accT[mt][jn][0], accT[mt][jn][1]);
                *(float2*)&Tp[(dk0 + g + 8) * HD + dv] =
                    make_float2(accT[mt][jn][2], accT[mt][jn][3]);
            }
        }
        __threadfence();
        __syncthreads();
        if (tid == 0) atomicAdd(&g_cnt[n], 1);
        __syncthreads();
    }

    // ================= Phase 1: q tile GEMM =================
    float acc[4][4][4];
#pragma unroll
    for (int i = 0; i < 4; i++)
#pragma unroll
        for (int j = 0; j < 4; j++)
#pragma unroll
            for (int f = 0; f < 4; f++) acc[i][j][f] = 0.f;

    PJ_FILL(0, 0,  n0);
    PJ_FILL(1, 64, n0);

    const int NKT = E_DIM / 64;
    for (int kt = 0; kt < NKT; kt++) {
        const int st = kt % 3;
        if (kt < NKT - 1) { CP_WAIT(1); } else { CP_WAIT(0); }
        __syncthreads();

        const __half* Xs = sh + st * PJ_STG;
        const __half* Ws = Xs + 128 * PJ_LD;

#pragma unroll
        for (int ks = 0; ks < 4; ks++) {
            const int kb = ks * 16;
            unsigned a[4][4];
#pragma unroll
            for (int i = 0; i < 4; i++) {
                int row = warpM * 64 + i * 16 + ((quad & 1) << 3) + rr;
                int col = kb + ((quad >> 1) << 3);
                LDSM_X4(a[i][0], a[i][1], a[i][2], a[i][3],
                        su32(Xs + row * PJ_LD + col));
            }
#pragma unroll
            for (int jj = 0; jj < 2; jj++) {
                int nrow = warpN * 32 + jj * 16 + ((quad >> 1) << 3) + rr;
                int col  = kb + ((quad & 1) << 3);
                unsigned b0, b1, b2, b3;
                LDSM_X4(b0, b1, b2, b3, su32(Ws + nrow * PJ_LD + col));
#pragma unroll
                for (int i = 0; i < 4; i++) {
                    MMA16(acc[i][2 * jj],     a[i], b0, b1);
                    MMA16(acc[i][2 * jj + 1], a[i], b2, b3);
                }
            }
        }

        if (kt + 2 < NKT) PJ_FILL((kt + 2) % 3, (kt + 2) * 64, n0);
    }

    // ================= Phase 2: consumer — fused epilogue =================
    __syncthreads();                       // stage buffers free
    __half* Qst = sh;                      // [128][QST_LD]
    __half* Tst = sh + 128 * QST_LD;       // [64][72]

    // stage q tile (+bq) to Qst first (overlaps any residual spin)
#pragma unroll
    for (int j = 0; j < 4; j++) {
        int col = warpN * 32 + j * 8 + tg * 2;          // 0..127 local
        float b0 = bq[n0 + col], b1 = bq[n0 + col + 1];
#pragma unroll
        for (int i = 0; i < 4; i++) {
            int rl = warpM * 64 + i * 16;
            *(__half2*)&Qst[(rl + g) * QST_LD + col] =
                __floats2half2_rn(acc[i][j][0] + b0, acc[i][j][1] + b1);
            *(__half2*)&Qst[(rl + g + 8) * QST_LD + col] =
                __floats2half2_rn(acc[i][j][2] + b0, acc[i][j][3] + b1);
        }
    }

    // spin until all 8 partials for this n are published
    if (tid == 0) {
        while (atomicAdd(&g_cnt[n], 0) < 8) { }
    }
    __syncthreads();
    __threadfence();

    // reduce 8 partials -> Tst (f16, x0.125)
    {
        const float4* P = (const float4*)(g_Tp + (size_t)n * 8 * HD * HD);
#pragma unroll
        for (int t = 0; t < 4; t++) {
            int slot = tid + t * 256;        // 0..1023 float4 slots
            float4 s0 = P[slot];
#pragma unroll
            for (int p = 1; p < 8; p++) {
                float4 q = P[p * 1024 + slot];
                s0.x += q.x; s0.y += q.y; s0.z += q.z; s0.w += q.w;
            }
            int row = slot >> 4, col = (slot & 15) * 4;
            *(__half2*)&Tst[row * 72 + col] =
                __floats2half2_rn(s0.x * 0.125f, s0.y * 0.125f);
            *(__half2*)&Tst[row * 72 + col + 2] =
                __floats2half2_rn(s0.z * 0.125f, s0.w * 0.125f);
        }
    }
    __syncthreads();

    // warp w: head hl = w>>2, rows mb = (w&3)*32 .. +32
    const int hl = warp >> 2;
    const int mb = (warp & 3) * 32;

    float accF[2][4][2][4];
#pragma unroll
    for (int i = 0; i < 2; i++)
#pragma unroll
        for (int jj = 0; jj < 4; jj++)
#pragma unroll
            for (int jn = 0; jn < 2; jn++)
#pragma unroll
                for (int f = 0; f < 4; f++) accF[i][jj][jn][f] = 0.f;

#pragma unroll
    for (int k = 0; k < 4; k++) {
        const int kb = k * 16;
        unsigned a[2][4];
#pragma unroll
        for (int i = 0; i < 2; i++) {
            int row = mb + i * 16 + ((quad & 1) << 3) + rr;
            int col = hl * 64 + kb + ((quad >> 1) << 3);
            LDSM_X4(a[i][0], a[i][1], a[i][2], a[i][3],
                    su32(Qst + row * QST_LD + col));
        }
#pragma unroll
        for (int jj = 0; jj < 4; jj++) {
            int trow = kb + ((quad & 1) << 3) + rr;
            int tcol = jj * 16 + ((quad >> 1) << 3);
            unsigned v0, v1, v2, v3;
            LDSM_X4T(v0, v1, v2, v3, su32(Tst + trow * 72 + tcol));
#pragma unroll
            for (int i = 0; i < 2; i++) {
                MMA16(accF[i][jj][0], a[i], v0, v1);
                MMA16(accF[i][jj][1], a[i], v2, v3);
            }
        }
    }

    // store: out[(16*(m0+mloc) + h0+hl)*64 + d]
#pragma unroll
    for (int i = 0; i < 2; i++) {
        int mA = m0 + mb + i * 16 + g;
        int mB = mA + 8;
        size_t RA = (size_t)(16 * mA + h0 + hl) * HD;
        size_t RB = (size_t)(16 * mB + h0 + hl) * HD;
#pragma unroll
        for (int jj = 0; jj < 4; jj++) {
#pragma unroll
            for (int jn = 0; jn < 2; jn++) {
                int d = jj * 16 + jn * 8 + tg * 2;
                *(float2*)&out[RA + d] =
                    make_float2(accF[i][jj][jn][0], accF[i][jj][jn][1]);
                *(float2*)&out[RB + d] =
                    make_float2(accF[i][jj][jn][2], accF[i][jj][jn][3]);
            }
        }
    }
}

// ---------------------------------------------------------------------------
extern "C" void kernel_launch(void* const* d_in, const int* in_sizes, int n_in,
                              void* d_out, int out_size)
{
    const float* x  = (const float*)d_in[0];
    const float* Wq = (const float*)d_in[1];
    const float* bq = (const float*)d_in[2];
    const float* Wk = (const float*)d_in[3];
    const float* bk = (const float*)d_in[4];
    const float* Wv = (const float*)d_in[5];
    const float* bv = (const float*)d_in[6];
    float* out = (float*)d_out;

    cudaFuncSetAttribute(proj_kv_kernel,
                         cudaFuncAttributeMaxDynamicSharedMemorySize, PJ_SMEM);
    cudaFuncSetAttribute(proj_q_kernel,
                         cudaFuncAttributeMaxDynamicSharedMemorySize, PJ_SMEM);

    cvt_kernel<<<1536, 256>>>(x, Wk, Wv);

    proj_kv_kernel<<<dim3(2 * E_DIM / 128, M_TOT / 128), 256, PJ_SMEM>>>(Wq, bk, bv);

    proj_q_kernel<<<dim3(E_DIM / 128, M_TOT / 128), 256, PJ_SMEM>>>(bq, out);
}

// round 16
// speedup vs baseline: 1.0642x; 1.0032x over previous
#include <cuda_runtime.h>
#include <cuda_fp16.h>

#define E_DIM   1024
#define M_TOT   4096
#define SEQ     2048
#define NBATCH  32
#define HD      64

// scratch
__device__ __half g_xh[M_TOT * E_DIM];
__device__ __half g_Wh[3 * E_DIM * E_DIM];    // Wq | Wk | Wv stacked [3072,1024]
__device__ __half g_Kh[M_TOT * E_DIM];
__device__ __half g_Vh[M_TOT * E_DIM];
__device__ float  g_Tp[NBATCH * 8 * HD * HD]; // 8 partials of K^T V per n
__device__ int    g_cnt[NBATCH];              // T-partial producers (8 per n)

__device__ __forceinline__ unsigned su32(const void* p) {
    return (unsigned)__cvta_generic_to_shared(p);
}
#define CPA16(d, s) \
    asm volatile("cp.async.cg.shared.global [%0],[%1],16;" :: "r"(d), "l"(s))
#define CP_COMMIT() asm volatile("cp.async.commit_group;")
#define CP_WAIT(n)  asm volatile("cp.async.wait_group %0;" :: "n"(n))

#define LDSM_X4(r0, r1, r2, r3, p) \
    asm volatile("ldmatrix.sync.aligned.m8n8.x4.shared.b16 {%0,%1,%2,%3},[%4];" \
                 : "=r"(r0), "=r"(r1), "=r"(r2), "=r"(r3) : "r"(p))
#define LDSM_X4T(r0, r1, r2, r3, p) \
    asm volatile("ldmatrix.sync.aligned.m8n8.x4.trans.shared.b16 {%0,%1,%2,%3},[%4];" \
                 : "=r"(r0), "=r"(r1), "=r"(r2), "=r"(r3) : "r"(p))

#define MMA16(c, a, b0_, b1_) \
    asm volatile("mma.sync.aligned.m16n8k16.row.col.f32.f16.f16.f32 " \
                 "{%0,%1,%2,%3},{%4,%5,%6,%7},{%8,%9},{%0,%1,%2,%3};" \
                 : "+f"((c)[0]), "+f"((c)[1]), "+f"((c)[2]), "+f"((c)[3]) \
                 : "r"((a)[0]), "r"((a)[1]), "r"((a)[2]), "r"((a)[3]), \
                   "r"(b0_), "r"(b1_))

// Convert two float4 (8 f32) to one uint4 (8 packed halfs).
__device__ __forceinline__ uint4 f8_to_h8(float4 a, float4 b) {
    __half2 h0 = __floats2half2_rn(a.x, a.y);
    __half2 h1 = __floats2half2_rn(a.z, a.w);
    __half2 h2 = __floats2half2_rn(b.x, b.y);
    __half2 h3 = __floats2half2_rn(b.z, b.w);
    uint4 u;
    u.x = *(unsigned*)&h0; u.y = *(unsigned*)&h1;
    u.z = *(unsigned*)&h2; u.w = *(unsigned*)&h3;
    return u;
}
__device__ __forceinline__ uint2 f4_to_h4(float4 v) {
    __half2 h0 = __floats2half2_rn(v.x, v.y);
    __half2 h1 = __floats2half2_rn(v.z, v.w);
    uint2 u;
    u.x = *(unsigned*)&h0; u.y = *(unsigned*)&h1;
    return u;
}

// ---------------------------------------------------------------------------
// cvt: f32 -> f16 for x, Wk, Wv (Wq folded into proj_kv). MLP=8 loads:
// each thread does 4 uint4 slots = 8 float4 loads, all independent.
// blocks [0,512): x   [512,640): Wk   [640,768): Wv. Resets counters.
// ---------------------------------------------------------------------------
__global__ void cvt_kernel(const float* __restrict__ x,
                           const float* __restrict__ wk,
                           const float* __restrict__ wv)
{
    if (blockIdx.x == 0 && threadIdx.x < NBATCH) g_cnt[threadIdx.x] = 0;
    const int b = blockIdx.x;
    const float* s; __half* d; int base;   // base in uint4 slots (1024/block)
    if (b < 512)      { s = x;  d = g_xh;                     base = b * 1024; }
    else if (b < 640) { s = wk; d = g_Wh + E_DIM * E_DIM;     base = (b - 512) * 1024; }
    else              { s = wv; d = g_Wh + 2 * E_DIM * E_DIM; base = (b - 640) * 1024; }
    const float4* S4 = (const float4*)s;
    uint4* D = (uint4*)d;
    float4 a[4], bb[4];
#pragma unroll
    for (int t = 0; t < 4; t++) {
        int slot = base + threadIdx.x + t * 256;
        a[t]  = S4[2 * slot];
        bb[t] = S4[2 * slot + 1];
    }
#pragma unroll
    for (int t = 0; t < 4; t++) {
        int slot = base + threadIdx.x + t * 256;
        D[slot] = f8_to_h8(a[t], bb[t]);
    }
}

// ---------------------------------------------------------------------------
// proj_kv: C[4096,2048] = X @ [Wk;Wv]^T + bias  -> g_Kh / g_Vh (f16)
// CTA 128x128, BK=64, 3-stage cp.async, 8 warps (2x4). grid (16, 32).
// Prologue: sync-free Wq conversion, 2 rows per CTA.
// ---------------------------------------------------------------------------
#define PJ_LD   72
#define PJ_STG  ((128 + 128) * PJ_LD)
#define PJ_SMEM (3 * PJ_STG * (int)sizeof(__half))   // 110592 B

__global__ __launch_bounds__(256, 2) void proj_kv_kernel(
    const float* __restrict__ wq,
    const float* __restrict__ bk, const float* __restrict__ bv)
{
    extern __shared__ __half sh[];

    const int tid  = threadIdx.x, lane = tid & 31;
    const int warp = tid >> 5, warpM = warp >> 2, warpN = warp & 3;
    const int g = lane >> 2, tg = lane & 3;
    const int quad = lane >> 3, rr = lane & 7;
    const int m0 = blockIdx.y * 128;
    const int n0 = blockIdx.x * 128;      // 0..2047 over Wk|Wv

    // ---- sync-free distributed Wq conversion: 2 rows per CTA ----
    {
        const int cid = blockIdx.x + (blockIdx.y << 4);   // 0..511
        const float4* W4 = (const float4*)wq;
        uint2* Wd = (uint2*)g_Wh;
#pragma unroll
        for (int r = 0; r < 2; r++) {
            int row = cid * 2 + r;
            Wd[(size_t)row * 256 + tid] = f4_to_h4(W4[(size_t)row * 256 + tid]);
        }
    }

    float acc[4][4][4];
#pragma unroll
    for (int i = 0; i < 4; i++)
#pragma unroll
        for (int j = 0; j < 4; j++)
#pragma unroll
            for (int f = 0; f < 4; f++) acc[i][j][f] = 0.f;

#define PJ_FILL(st, k0, WROW0)                                                \
    do {                                                                      \
        __half* Xs = sh + (st) * PJ_STG;                                      \
        __half* Ws = Xs + 128 * PJ_LD;                                        \
        _Pragma("unroll")                                                     \
        for (int t = 0; t < 4; t++) {                                         \
            int seg = tid + t * 256;                                          \
            int row = seg >> 3, c16 = seg & 7;                                \
            CPA16(su32(Xs + row * PJ_LD + c16 * 8),                           \
                  &g_xh[(size_t)(m0 + row) * E_DIM + (k0) + c16 * 8]);        \
        }                                                                     \
        _Pragma("unroll")                                                     \
        for (int t = 0; t < 4; t++) {                                         \
            int seg = tid + t * 256;                                          \
            int row = seg >> 3, c16 = seg & 7;                                \
            CPA16(su32(Ws + row * PJ_LD + c16 * 8),                           \
                  &g_Wh[(size_t)((WROW0) + row) * E_DIM + (k0) + c16 * 8]);   \
        }                                                                     \
        CP_COMMIT();                                                          \
    } while (0)

    PJ_FILL(0, 0,  E_DIM + n0);
    PJ_FILL(1, 64, E_DIM + n0);

    const int NKT = E_DIM / 64;
    for (int kt = 0; kt < NKT; kt++) {
        const int st = kt % 3;
        if (kt < NKT - 1) { CP_WAIT(1); } else { CP_WAIT(0); }
        __syncthreads();

        const __half* Xs = sh + st * PJ_STG;
        const __half* Ws = Xs + 128 * PJ_LD;

#pragma unroll
        for (int ks = 0; ks < 4; ks++) {
            const int kb = ks * 16;
            unsigned a[4][4];
#pragma unroll
            for (int i = 0; i < 4; i++) {
                int row = warpM * 64 + i * 16 + ((quad & 1) << 3) + rr;
                int col = kb + ((quad >> 1) << 3);
                LDSM_X4(a[i][0], a[i][1], a[i][2], a[i][3],
                        su32(Xs + row * PJ_LD + col));
            }
#pragma unroll
            for (int jj = 0; jj < 2; jj++) {
                int nrow = warpN * 32 + jj * 16 + ((quad >> 1) << 3) + rr;
                int col  = kb + ((quad & 1) << 3);
                unsigned b0, b1, b2, b3;
                LDSM_X4(b0, b1, b2, b3, su32(Ws + nrow * PJ_LD + col));
#pragma unroll
                for (int i = 0; i < 4; i++) {
                    MMA16(acc[i][2 * jj],     a[i], b0, b1);
                    MMA16(acc[i][2 * jj + 1], a[i], b2, b3);
                }
            }
        }

        if (kt + 2 < NKT) PJ_FILL((kt + 2) % 3, (kt + 2) * 64, E_DIM + n0);
    }

    const int which = n0 >> 10;           // 0 -> K, 1 -> V
    const int nbase = n0 & 1023;
    const float* bias = which ? bv : bk;
    __half* C = which ? g_Vh : g_Kh;

#pragma unroll
    for (int j = 0; j < 4; j++) {
        int col = nbase + warpN * 32 + j * 8 + tg * 2;
        float b0 = bias[col], b1 = bias[col + 1];
#pragma unroll
        for (int i = 0; i < 4; i++) {
            int rbase = m0 + warpM * 64 + i * 16;
            *(__half2*)&C[(size_t)(rbase + g) * E_DIM + col] =
                __floats2half2_rn(acc[i][j][0] + b0, acc[i][j][1] + b1);
            *(__half2*)&C[(size_t)(rbase + g + 8) * E_DIM + col] =
                __floats2half2_rn(acc[i][j][2] + b0, acc[i][j][3] + b1);
        }
    }
}

// ---------------------------------------------------------------------------
// proj_q: fused producer/consumer kernel. grid (8, 32), all 256 CTAs
// co-resident (occ=2 by launch_bounds + smem).
// Phase 0 (producer): partial T over s'-rows [ch*256,+256) of batch n,
//                     processed in TWO 128-row chunks (halves syncs);
//                     store f32 partial; fence; count++.
// Phase 1: q tile = X @ Wq^T (128x128 = 2 heads), 3-stage pipeline.
// Phase 2 (consumer): spin cnt[n]==8; reduce 8 partials *0.125 -> f16 smem;
//                     out rows R=16m+h: out[R] = q64(m,h) @ T[n].
// ---------------------------------------------------------------------------
#define QST_LD 136
#define KV_LD  72

__global__ __launch_bounds__(256, 2) void proj_q_kernel(
    const float* __restrict__ bq, float* __restrict__ out)
{
    extern __shared__ __half sh[];

    const int tid  = threadIdx.x, lane = tid & 31;
    const int warp = tid >> 5, warpM = warp >> 2, warpN = warp & 3;
    const int g = lane >> 2, tg = lane & 3;
    const int quad = lane >> 3, rr = lane & 7;
    const int ch = blockIdx.x;            // partial chunk AND n-tile (h0 = 2*ch)
    const int n  = blockIdx.y;            // batch n AND m-tile (m0 = 128*n)
    const int m0 = n * 128;
    const int n0 = ch * 128;
    const int h0 = n0 >> 6;

    // ================= Phase 0: producer — partial T[n][ch] ================
    {
        const __half* Kg = g_Kh + (size_t)n * SEQ * HD + (size_t)ch * 256 * HD;
        const __half* Vg = g_Vh + (size_t)n * SEQ * HD + (size_t)ch * 256 * HD;
        __half* Ksb = sh;                          // [2][128*KV_LD]
        __half* Vsb = sh + 2 * 128 * KV_LD;        // [2][128*KV_LD]

        const int mh = (warp >> 2) * 32;
        const int nb = (warp & 3) * 16;

        float accT[2][2][4];
#pragma unroll
        for (int mt = 0; mt < 2; mt++)
#pragma unroll
            for (int jn = 0; jn < 2; jn++)
#pragma unroll
                for (int f = 0; f < 4; f++) accT[mt][jn][f] = 0.f;

        // fill one 128-row chunk of K and V (1024 segs each -> 4/thread)
#define KVP_ISSUE(buf, k0)                                                    \
        do {                                                                  \
            _Pragma("unroll")                                                 \
            for (int t = 0; t < 4; t++) {                                     \
                int seg = tid + t * 256;                                      \
                int row = seg >> 3, s8 = seg & 7;                             \
                CPA16(su32(Ksb + (buf) * 128 * KV_LD + row * KV_LD + s8 * 8), \
                      &Kg[(size_t)((k0) + row) * HD + s8 * 8]);               \
                CPA16(su32(Vsb + (buf) * 128 * KV_LD + row * KV_LD + s8 * 8), \
                      &Vg[(size_t)((k0) + row) * HD + s8 * 8]);               \
            }                                                                 \
            CP_COMMIT();                                                      \
        } while (0)

        KVP_ISSUE(0, 0);
        KVP_ISSUE(1, 128);

        for (int c = 0; c < 2; c++) {
            if (c == 0) { CP_WAIT(1); } else { CP_WAIT(0); }
            __syncthreads();

            const __half* Ksx = Ksb + c * 128 * KV_LD;
            const __half* Vsx = Vsb + c * 128 * KV_LD;
#pragma unroll
            for (int ks = 0; ks < 8; ks++) {
                const int sb = ks * 16;
                unsigned a[2][4];
#pragma unroll
                for (int mt = 0; mt < 2; mt++) {
                    int row = sb + ((quad >> 1) << 3) + rr;
                    int col = mh + mt * 16 + ((quad & 1) << 3);
                    LDSM_X4T(a[mt][0], a[mt][1], a[mt][2], a[mt][3],
                             su32(Ksx + row * KV_LD + col));
                }
                int vrow = sb + ((quad & 1) << 3) + rr;
                int vcol = nb + ((quad >> 1) << 3);
                unsigned v0, v1, v2, v3;
                LDSM_X4T(v0, v1, v2, v3, su32(Vsx + vrow * KV_LD + vcol));
#pragma unroll
                for (int mt = 0; mt < 2; mt++) {
                    MMA16(accT[mt][0], a[mt], v0, v1);
                    MMA16(accT[mt][1], a[mt], v2, v3);
                }
            }
        }

        float* Tp = g_Tp + ((size_t)(n * 8 + ch)) * HD * HD;
#pragma unroll
        for (int mt = 0; mt < 2; mt++) {
            int dk0 = mh + mt * 16;
#pragma unroll
            for (int jn = 0; jn < 2; jn++) {
                int dv = nb + jn * 8 + tg * 2;
                *(float2*)&Tp[(dk0 + g) * HD + dv] =
                    make_float2(accT[mt][jn][0], accT[mt][jn][1]);
                *(float2*)&Tp[(dk0 + g + 8) * HD + dv] =
                    make_float2(accT[mt][jn][2], accT[mt][jn][3]);
            }
        }
        __threadfence();
        __syncthreads();
        if (tid == 0) atomicAdd(&g_cnt[n], 1);
        __syncthreads();
    }

    // ================= Phase 1: q tile GEMM =================
    float acc[4][4][4];
#pragma unroll
    for (int i = 0; i < 4; i++)
#pragma unroll
        for (int j = 0; j < 4; j++)
#pragma unroll
            for (int f = 0; f < 4; f++) acc[i][j][f] = 0.f;

    PJ_FILL(0, 0,  n0);
    PJ_FILL(1, 64, n0);

    const int NKT = E_DIM / 64;
    for (int kt = 0; kt < NKT; kt++) {
        const int st = kt % 3;
        if (kt < NKT - 1) { CP_WAIT(1); } else { CP_WAIT(0); }
        __syncthreads();

        const __half* Xs = sh + st * PJ_STG;
        const __half* Ws = Xs + 128 * PJ_LD;

#pragma unroll
        for (int ks = 0; ks < 4; ks++) {
            const int kb = ks * 16;
            unsigned a[4][4];
#pragma unroll
            for (int i = 0; i < 4; i++) {
                int row = warpM * 64 + i * 16 + ((quad & 1) << 3) + rr;
                int col = kb + ((quad >> 1) << 3);
                LDSM_X4(a[i][0], a[i][1], a[i][2], a[i][3],
                        su32(Xs + row * PJ_LD + col));
            }
#pragma unroll
            for (int jj = 0; jj < 2; jj++) {
                int nrow = warpN * 32 + jj * 16 + ((quad >> 1) << 3) + rr;
                int col  = kb + ((quad & 1) << 3);
                unsigned b0, b1, b2, b3;
                LDSM_X4(b0, b1, b2, b3, su32(Ws + nrow * PJ_LD + col));
#pragma unroll
                for (int i = 0; i < 4; i++) {
                    MMA16(acc[i][2 * jj],     a[i], b0, b1);
                    MMA16(acc[i][2 * jj + 1], a[i], b2, b3);
                }
            }
        }

        if (kt + 2 < NKT) PJ_FILL((kt + 2) % 3, (kt + 2) * 64, n0);
    }

    // ================= Phase 2: consumer — fused epilogue =================
    __syncthreads();                       // stage buffers free
    __half* Qst = sh;                      // [128][QST_LD]
    __half* Tst = sh + 128 * QST_LD;       // [64][72]

    // stage q tile (+bq) to Qst first (overlaps any residual spin)
#pragma unroll
    for (int j = 0; j < 4; j++) {
        int col = warpN * 32 + j * 8 + tg * 2;          // 0..127 local
        float b0 = bq[n0 + col], b1 = bq[n0 + col + 1];
#pragma unroll
        for (int i = 0; i < 4; i++) {
            int rl = warpM * 64 + i * 16;
            *(__half2*)&Qst[(rl + g) * QST_LD + col] =
                __floats2half2_rn(acc[i][j][0] + b0, acc[i][j][1] + b1);
            *(__half2*)&Qst[(rl + g + 8) * QST_LD + col] =
                __floats2half2_rn(acc[i][j][2] + b0, acc[i][j][3] + b1);
        }
    }

    // spin until all 8 partials for this n are published
    if (tid == 0) {
        while (atomicAdd(&g_cnt[n], 0) < 8) { }
    }
    __syncthreads();
    __threadfence();

    // reduce 8 partials -> Tst (f16, x0.125)
    {
        const float4* P = (const float4*)(g_Tp + (size_t)n * 8 * HD * HD);
#pragma unroll
        for (int t = 0; t < 4; t++) {
            int slot = tid + t * 256;        // 0..1023 float4 slots
            float4 s0 = P[slot];
#pragma unroll
            for (int p = 1; p < 8; p++) {
                float4 q = P[p * 1024 + slot];
                s0.x += q.x; s0.y += q.y; s0.z += q.z; s0.w += q.w;
            }
            int row = slot >> 4, col = (slot & 15) * 4;
            *(__half2*)&Tst[row * 72 + col] =
                __floats2half2_rn(s0.x * 0.125f, s0.y * 0.125f);
            *(__half2*)&Tst[row * 72 + col + 2] =
                __floats2half2_rn(s0.z * 0.125f, s0.w * 0.125f);
        }
    }
    __syncthreads();

    // warp w: head hl = w>>2, rows mb = (w&3)*32 .. +32
    const int hl = warp >> 2;
    const int mb = (warp & 3) * 32;

    float accF[2][4][2][4];
#pragma unroll
    for (int i = 0; i < 2; i++)
#pragma unroll
        for (int jj = 0; jj < 4; jj++)
#pragma unroll
            for (int jn = 0; jn < 2; jn++)
#pragma unroll
                for (int f = 0; f < 4; f++) accF[i][jj][jn][f] = 0.f;

#pragma unroll
    for (int k = 0; k < 4; k++) {
        const int kb = k * 16;
        unsigned a[2][4];
#pragma unroll
        for (int i = 0; i < 2; i++) {
            int row = mb + i * 16 + ((quad & 1) << 3) + rr;
            int col = hl * 64 + kb + ((quad >> 1) << 3);
            LDSM_X4(a[i][0], a[i][1], a[i][2], a[i][3],
                    su32(Qst + row * QST_LD + col));
        }
#pragma unroll
        for (int jj = 0; jj < 4; jj++) {
            int trow = kb + ((quad & 1) << 3) + rr;
            int tcol = jj * 16 + ((quad >> 1) << 3);
            unsigned v0, v1, v2, v3;
            LDSM_X4T(v0, v1, v2, v3, su32(Tst + trow * 72 + tcol));
#pragma unroll
            for (int i = 0; i < 2; i++) {
                MMA16(accF[i][jj][0], a[i], v0, v1);
                MMA16(accF[i][jj][1], a[i], v2, v3);
            }
        }
    }

    // store: out[(16*(m0+mloc) + h0+hl)*64 + d]
#pragma unroll
    for (int i = 0; i < 2; i++) {
        int mA = m0 + mb + i * 16 + g;
        int mB = mA + 8;
        size_t RA = (size_t)(16 * mA + h0 + hl) * HD;
        size_t RB = (size_t)(16 * mB + h0 + hl) * HD;
#pragma unroll
        for (int jj = 0; jj < 4; jj++) {
#pragma unroll
            for (int jn = 0; jn < 2; jn++) {
                int d = jj * 16 + jn * 8 + tg * 2;
                *(float2*)&out[RA + d] =
                    make_float2(accF[i][jj][jn][0], accF[i][jj][jn][1]);
                *(float2*)&out[RB + d] =
                    make_float2(accF[i][jj][jn][2], accF[i][jj][jn][3]);
            }
        }
    }
}

// ---------------------------------------------------------------------------
extern "C" void kernel_launch(void* const* d_in, const int* in_sizes, int n_in,
                              void* d_out, int out_size)
{
    const float* x  = (const float*)d_in[0];
    const float* Wq = (const float*)d_in[1];
    const float* bq = (const float*)d_in[2];
    const float* Wk = (const float*)d_in[3];
    const float* bk = (const float*)d_in[4];
    const float* Wv = (const float*)d_in[5];
    const float* bv = (const float*)d_in[6];
    float* out = (float*)d_out;

    cudaFuncSetAttribute(proj_kv_kernel,
                         cudaFuncAttributeMaxDynamicSharedMemorySize, PJ_SMEM);
    cudaFuncSetAttribute(proj_q_kernel,
                         cudaFuncAttributeMaxDynamicSharedMemorySize, PJ_SMEM);

    cvt_kernel<<<768, 256>>>(x, Wk, Wv);

    proj_kv_kernel<<<dim3(2 * E_DIM / 128, M_TOT / 128), 256, PJ_SMEM>>>(Wq, bk, bv);

    proj_q_kernel<<<dim3(E_DIM / 128, M_TOT / 128), 256, PJ_SMEM>>>(bq, out);
}